// round 1
// baseline (speedup 1.0000x reference)
#include <cuda_runtime.h>
#include <math.h>

#define NE  256
#define DD  256
#define NH  4
#define DHD 64
#define NL  2
#define P_TOTAL (NE*(NE-1)/2)        /* 32640 */
#define PPB 8
#define NBLOCKS (P_TOTAL/PPB)        /* 4080 */
#define SMEM_BYTES (4*PPB*2*256*4)   /* 65536: h,q,k,v */

// ---------------- scratch (device globals; no allocations) ----------------
__device__ float2 g_A[NE*NE];
__device__ double g_acc[2];          // bosonic log sum (re, im)
__device__ double g_lu_logabs, g_lu_arg;
__device__ int    g_lu_par;

__device__ __forceinline__ float f4c(const float4& v, int u) {
    return u==0 ? v.x : (u==1 ? v.y : (u==2 ? v.z : v.w));
}

// out[p][s][tid] accumulator: acc[p][s] = sum_e in[p][s][e] * W[e*256+tid]
__device__ __forceinline__ void gemm256(const float* __restrict__ W,
                                        const float* in, float acc[PPB][2], int tid)
{
    #pragma unroll
    for (int p = 0; p < PPB; p++) { acc[p][0] = 0.f; acc[p][1] = 0.f; }
    for (int e = 0; e < 256; e += 4) {
        float4 hv[PPB][2];
        #pragma unroll
        for (int p = 0; p < PPB; p++) {
            hv[p][0] = *(const float4*)(in + (p*2+0)*256 + e);
            hv[p][1] = *(const float4*)(in + (p*2+1)*256 + e);
        }
        #pragma unroll
        for (int u = 0; u < 4; u++) {
            float w = __ldg(W + (e+u)*256 + tid);
            #pragma unroll
            for (int p = 0; p < PPB; p++) {
                acc[p][0] = fmaf(f4c(hv[p][0], u), w, acc[p][0]);
                acc[p][1] = fmaf(f4c(hv[p][1], u), w, acc[p][1]);
            }
        }
    }
}

__device__ __forceinline__ void layernorm(float* shh,
                                          const float* __restrict__ sc,
                                          const float* __restrict__ bi,
                                          float red[PPB][2][2][8], int tid)
{
    int lane = tid & 31, wrp = tid >> 5;
    float x[PPB][2];
    #pragma unroll
    for (int p = 0; p < PPB; p++) {
        #pragma unroll
        for (int s = 0; s < 2; s++) {
            float v = shh[(p*2+s)*256 + tid];
            x[p][s] = v;
            float s1 = v, s2 = v*v;
            #pragma unroll
            for (int off = 16; off; off >>= 1) {
                s1 += __shfl_xor_sync(0xffffffffu, s1, off);
                s2 += __shfl_xor_sync(0xffffffffu, s2, off);
            }
            if (lane == 0) { red[p][s][0][wrp] = s1; red[p][s][1][wrp] = s2; }
        }
    }
    __syncthreads();
    float scv = __ldg(sc + tid), biv = __ldg(bi + tid);
    #pragma unroll
    for (int p = 0; p < PPB; p++) {
        #pragma unroll
        for (int s = 0; s < 2; s++) {
            float s1 = 0.f, s2 = 0.f;
            #pragma unroll
            for (int w = 0; w < 8; w++) { s1 += red[p][s][0][w]; s2 += red[p][s][1][w]; }
            float m   = s1 * (1.f/256.f);
            float var = s2 * (1.f/256.f) - m*m;
            shh[(p*2+s)*256 + tid] = (x[p][s] - m) * rsqrtf(var + 1e-5f) * scv + biv;
        }
    }
    __syncthreads();
}

// ---------------- pair transformer + orbitals -> antisymmetric A ----------
__global__ void __launch_bounds__(256, 2) pair_kernel(
    const float* __restrict__ electrons,
    const float* __restrict__ W_in,
    const float* __restrict__ Wq, const float* __restrict__ bq,
    const float* __restrict__ Wk, const float* __restrict__ bk,
    const float* __restrict__ Wv, const float* __restrict__ bv,
    const float* __restrict__ Wo, const float* __restrict__ bo,
    const float* __restrict__ W1, const float* __restrict__ ln1_s, const float* __restrict__ ln1_b,
    const float* __restrict__ W2, const float* __restrict__ b2,
    const float* __restrict__ ln2_s, const float* __restrict__ ln2_b,
    const float* __restrict__ Worb_r, const float* __restrict__ Worb_i)
{
    extern __shared__ float smem[];
    float* shh = smem;
    float* shq = shh + PPB*2*256;
    float* shk = shq + PPB*2*256;
    float* shv = shk + PPB*2*256;

    __shared__ float s_attn[PPB][NH][2][2];
    __shared__ float s_feat[PPB][2][3];
    __shared__ float s_tp[PPB][2][2];
    __shared__ int   s_ij[PPB][2];
    __shared__ float s_red[PPB][2][2][8];
    __shared__ float s_orb[PPB][8];

    int tid = threadIdx.x;

    if (tid < PPB) {
        long long p = (long long)blockIdx.x * PPB + tid;
        double pd = (double)p;
        int i = (int)floor((2.0*NE - 1.0 - sqrt((2.0*NE-1.0)*(2.0*NE-1.0) - 8.0*pd)) * 0.5);
        if (i < 0) i = 0;
        if (i > NE-2) i = NE-2;
        while (i > 0 && (long long)i*(2*NE-1-i)/2 > p) i--;
        while ((long long)(i+1)*(2*NE-1-(i+1))/2 <= p) i++;
        long long base = (long long)i*(2*NE-1-i)/2;
        int j = (int)(p - base) + i + 1;
        s_ij[tid][0] = i; s_ij[tid][1] = j;
    }
    __syncthreads();
    if (tid < PPB*2) {
        int p = tid >> 1, s = tid & 1;
        int e = s_ij[p][s];
        float th = electrons[2*e], ph = electrons[2*e+1];
        s_tp[p][s][0] = th; s_tp[p][s][1] = ph;
        float st, ct, sp, cp;
        sincosf(th, &st, &ct);
        sincosf(ph, &sp, &cp);
        s_feat[p][s][0] = ct;
        s_feat[p][s][1] = st*cp;
        s_feat[p][s][2] = st*sp;
    }
    __syncthreads();

    // h = feat @ W_in
    {
        float w0 = __ldg(W_in + tid), w1 = __ldg(W_in + 256 + tid), w2 = __ldg(W_in + 512 + tid);
        #pragma unroll
        for (int p = 0; p < PPB; p++)
            #pragma unroll
            for (int s = 0; s < 2; s++)
                shh[(p*2+s)*256 + tid] = s_feat[p][s][0]*w0 + s_feat[p][s][1]*w1 + s_feat[p][s][2]*w2;
    }
    __syncthreads();

    float acc[PPB][2];
    for (int l = 0; l < NL; l++) {
        const float* Wq_l = Wq + l*65536;  const float* bq_l = bq + l*256;
        const float* Wk_l = Wk + l*65536;  const float* bk_l = bk + l*256;
        const float* Wv_l = Wv + l*65536;  const float* bv_l = bv + l*256;
        const float* Wo_l = Wo + l*65536;  const float* bo_l = bo + l*256;
        const float* W1_l = W1 + l*65536;
        const float* W2_l = W2 + l*65536;  const float* b2_l = b2 + l*256;

        gemm256(Wq_l, shh, acc, tid);
        { float b = __ldg(bq_l + tid);
          #pragma unroll
          for (int p = 0; p < PPB; p++) { shq[(p*2+0)*256+tid] = acc[p][0]+b; shq[(p*2+1)*256+tid] = acc[p][1]+b; } }
        gemm256(Wk_l, shh, acc, tid);
        { float b = __ldg(bk_l + tid);
          #pragma unroll
          for (int p = 0; p < PPB; p++) { shk[(p*2+0)*256+tid] = acc[p][0]+b; shk[(p*2+1)*256+tid] = acc[p][1]+b; } }
        gemm256(Wv_l, shh, acc, tid);
        { float b = __ldg(bv_l + tid);
          #pragma unroll
          for (int p = 0; p < PPB; p++) { shv[(p*2+0)*256+tid] = acc[p][0]+b; shv[(p*2+1)*256+tid] = acc[p][1]+b; } }
        __syncthreads();

        // attention (seq len 2, 4 heads)
        if (tid < PPB*8) {
            int p = tid >> 3, r = tid & 7, hh = r >> 1, s = r & 1;
            const float* qv = shq + (p*2+s)*256 + hh*DHD;
            const float* k0 = shk + (p*2+0)*256 + hh*DHD;
            const float* k1 = shk + (p*2+1)*256 + hh*DHD;
            float l0 = 0.f, l1 = 0.f;
            #pragma unroll 8
            for (int d = 0; d < DHD; d++) { float q = qv[d]; l0 = fmaf(q, k0[d], l0); l1 = fmaf(q, k1[d], l1); }
            l0 *= 0.125f; l1 *= 0.125f;
            float mx = fmaxf(l0, l1);
            float e0 = expf(l0 - mx), e1 = expf(l1 - mx);
            float inv = 1.f / (e0 + e1);
            s_attn[p][hh][s][0] = e0 * inv;
            s_attn[p][hh][s][1] = e1 * inv;
        }
        __syncthreads();

        // o = attn @ v  (overwrite shq)
        {
            int hh = tid >> 6;
            #pragma unroll
            for (int p = 0; p < PPB; p++) {
                float v0 = shv[(p*2+0)*256+tid], v1 = shv[(p*2+1)*256+tid];
                shq[(p*2+0)*256+tid] = s_attn[p][hh][0][0]*v0 + s_attn[p][hh][0][1]*v1;
                shq[(p*2+1)*256+tid] = s_attn[p][hh][1][0]*v0 + s_attn[p][hh][1][1]*v1;
            }
        }
        __syncthreads();

        // mha = o @ Wo + bo -> shk
        gemm256(Wo_l, shq, acc, tid);
        { float b = __ldg(bo_l + tid);
          #pragma unroll
          for (int p = 0; p < PPB; p++) { shk[(p*2+0)*256+tid] = acc[p][0]+b; shk[(p*2+1)*256+tid] = acc[p][1]+b; } }
        __syncthreads();

        // h += mha @ W1
        gemm256(W1_l, shk, acc, tid);
        #pragma unroll
        for (int p = 0; p < PPB; p++) { shh[(p*2+0)*256+tid] += acc[p][0]; shh[(p*2+1)*256+tid] += acc[p][1]; }
        __syncthreads();
        layernorm(shh, ln1_s + l*256, ln1_b + l*256, s_red, tid);

        // h += tanh(h @ W2 + b2)
        gemm256(W2_l, shh, acc, tid);
        __syncthreads();
        { float b = __ldg(b2_l + tid);
          #pragma unroll
          for (int p = 0; p < PPB; p++) {
              shh[(p*2+0)*256+tid] += tanhf(acc[p][0] + b);
              shh[(p*2+1)*256+tid] += tanhf(acc[p][1] + b);
          } }
        __syncthreads();
        layernorm(shh, ln2_s + l*256, ln2_b + l*256, s_red, tid);
    }

    // orbital projections: 8 warps = (ri, s, c) combos
    {
        int wrp = tid >> 5, lane = tid & 31;
        const float* Ws = (wrp >= 4) ? Worb_i : Worb_r;
        int s = (wrp >> 1) & 1, c = wrp & 1;
        for (int p = 0; p < PPB; p++) {
            float sum = 0.f;
            for (int d = lane; d < 256; d += 32)
                sum = fmaf(shh[(p*2+s)*256 + d], __ldg(Ws + d*2 + c), sum);
            #pragma unroll
            for (int off = 16; off; off >>= 1) sum += __shfl_xor_sync(0xffffffffu, sum, off);
            if (lane == 0) s_orb[p][wrp] = sum;
        }
    }
    __syncthreads();

    if (tid < PPB) {
        int p = tid;
        float th0 = s_tp[p][0][0], ph0 = s_tp[p][0][1];
        float th1 = s_tp[p][1][0], ph1 = s_tp[p][1][1];
        float c0, s0, c1, s1;
        sincosf(0.5f*th0, &s0, &c0);
        sincosf(0.5f*th1, &s1, &c1);
        float hd = 0.5f*(ph0 - ph1);
        float chd, shd; sincosf(hd, &shd, &chd);
        float re = (c0*s1 - c1*s0) * chd;
        float im = (c0*s1 + c1*s0) * shd;
        float chord2 = re*re + im*im;
        float trunc = 1.f - expf(-100.f * chord2);
        float t2 = trunc * trunc;
        float a_r = s_orb[p][0], b_r = s_orb[p][1], c_r = s_orb[p][2], d_r = s_orb[p][3];
        float a_i = s_orb[p][4], b_i = s_orb[p][5], c_i = s_orb[p][6], d_i = s_orb[p][7];
        // det of [[o00,o01],[o10,o11]], o_sc = (real idx s*2+c, imag idx 4+s*2+c)
        float det_r = (a_r*d_r - a_i*d_i) - (b_r*c_r - b_i*c_i);
        float det_i = (a_r*d_i + a_i*d_r) - (b_r*c_i + b_i*c_r);
        det_r *= t2; det_i *= t2;
        int i = s_ij[p][0], j = s_ij[p][1];
        g_A[i*NE + j] = make_float2(det_r, det_i);
        g_A[j*NE + i] = make_float2(-det_r, -det_i);
    }
}

// ---------------- cusp matrix + bosonic log sum ---------------------------
__global__ void cusp_bos_kernel(const float* __restrict__ electrons)
{
    int i = blockIdx.x, j = threadIdx.x;
    __shared__ double s_red[2][8];
    float thi = electrons[2*i], phi_ = electrons[2*i+1];
    float thj = electrons[2*j], phj  = electrons[2*j+1];
    float ci, si, cj, sj;
    sincosf(0.5f*thi, &si, &ci);
    sincosf(0.5f*thj, &sj, &cj);
    float hd = 0.5f*(phi_ - phj);
    float chd, shd; sincosf(hd, &shd, &chd);
    float er = (ci*sj - si*cj) * chd;
    float ei = (ci*sj + si*cj) * shd;

    float eye = (i == j) ? 1.f : 0.f;
    float cr = er + eye, cim = ei;
    float rc2 = cr*cr + cim*cim;
    float g = expf(-100.f * rc2);
    float2 a = (i == j) ? make_float2(0.f, 0.f) : g_A[i*NE + j];
    a.x += cr * g;
    a.y += cim * g;
    g_A[i*NE + j] = a;

    double lr = 0.0, li = 0.0;
    if (i != j) {
        float rho2 = er*er + ei*ei;
        lr = 0.5 * log((double)(0.01f + rho2));   // log|masked|
        li = (double)atan2f(ei, er);              // arg(masked) = arg(elem)
    }
    int lane = j & 31, wrp = j >> 5;
    #pragma unroll
    for (int off = 16; off; off >>= 1) {
        lr += __shfl_xor_sync(0xffffffffu, lr, off);
        li += __shfl_xor_sync(0xffffffffu, li, off);
    }
    if (lane == 0) { s_red[0][wrp] = lr; s_red[1][wrp] = li; }
    __syncthreads();
    if (j == 0) {
        double a0 = 0.0, a1 = 0.0;
        #pragma unroll
        for (int w = 0; w < 8; w++) { a0 += s_red[0][w]; a1 += s_red[1][w]; }
        atomicAdd(&g_acc[0], a0);
        atomicAdd(&g_acc[1], a1);
    }
}

// ---------------- complex LU with partial pivoting (slogdet) --------------
__device__ __forceinline__ float2 cmul(float2 a, float2 b) {
    return make_float2(a.x*b.x - a.y*b.y, a.x*b.y + a.y*b.x);
}

__global__ void __launch_bounds__(1024) lu_kernel()
{
    __shared__ float2 s_prow[256];
    __shared__ float2 s_l[256];
    __shared__ float  s_mx[8];
    __shared__ int    s_mi[8];
    __shared__ float2 s_inv;
    __shared__ int    s_piv;
    int tid = threadIdx.x;
    double logabs = 0.0, argsum = 0.0;
    int par = 0;

    for (int k = 0; k < 256; k++) {
        if (tid < 256) {
            float v = -1.f; int idx = tid;
            if (tid >= k) { float2 a = g_A[tid*256 + k]; v = fabsf(a.x) + fabsf(a.y); }
            #pragma unroll
            for (int off = 16; off; off >>= 1) {
                float ov = __shfl_xor_sync(0xffffffffu, v, off);
                int   oi = __shfl_xor_sync(0xffffffffu, idx, off);
                if (ov > v) { v = ov; idx = oi; }
            }
            if ((tid & 31) == 0) { s_mx[tid>>5] = v; s_mi[tid>>5] = idx; }
        }
        __syncthreads();
        if (tid == 0) {
            float bv = -1.f; int bi = k;
            #pragma unroll
            for (int w = 0; w < 8; w++) if (s_mx[w] > bv) { bv = s_mx[w]; bi = s_mi[w]; }
            s_piv = bi;
        }
        __syncthreads();
        int pv = s_piv;
        if (pv != k && tid < 256) {
            float2 t = g_A[k*256 + tid];
            g_A[k*256 + tid] = g_A[pv*256 + tid];
            g_A[pv*256 + tid] = t;
        }
        __syncthreads();
        if (tid == 0) {
            if (pv != k) par ^= 1;
            float2 u = g_A[k*256 + k];
            double n2 = (double)u.x*u.x + (double)u.y*u.y;
            logabs += 0.5 * log(n2);
            argsum += atan2((double)u.y, (double)u.x);
            float d = u.x*u.x + u.y*u.y;
            s_inv = make_float2(u.x/d, -u.y/d);
        }
        __syncthreads();
        if (tid < 256) {
            s_prow[tid] = g_A[k*256 + tid];
            if (tid > k) {
                float2 l = cmul(g_A[tid*256 + k], s_inv);
                s_l[tid] = l;
                g_A[tid*256 + k] = l;
            }
        }
        __syncthreads();
        {
            int c = tid & 255, r0 = tid >> 8;
            if (c > k) {
                float2 pr = s_prow[c];
                #pragma unroll 4
                for (int i = k + 1 + r0; i < 256; i += 4) {
                    float2 l = s_l[i];
                    float2 a = g_A[i*256 + c];
                    a.x -= l.x*pr.x - l.y*pr.y;
                    a.y -= l.x*pr.y + l.y*pr.x;
                    g_A[i*256 + c] = a;
                }
            }
        }
        __syncthreads();
    }
    if (tid == 0) { g_lu_logabs = logabs; g_lu_arg = argsum; g_lu_par = par; }
}

// ---------------- init + finalize -----------------------------------------
__global__ void init_kernel() { g_acc[0] = 0.0; g_acc[1] = 0.0; }

__global__ void finalize_kernel(float* out)
{
    const double PI = 3.14159265358979323846;
    double logabs = g_lu_logabs;
    double arg = g_lu_arg + (g_lu_par ? PI : 0.0);
    double w = fmod(arg, 2.0*PI);
    if (w >  PI) w -= 2.0*PI;
    if (w <= -PI) w += 2.0*PI;
    out[0] = (float)(0.5*logabs + g_acc[0]);
    out[1] = (float)(0.5*w      + g_acc[1]);
}

// ---------------- launch ---------------------------------------------------
extern "C" void kernel_launch(void* const* d_in, const int* in_sizes, int n_in,
                              void* d_out, int out_size)
{
    const float* electrons = (const float*)d_in[0];
    const float* W_in   = (const float*)d_in[1];
    const float* Wq     = (const float*)d_in[2];
    const float* bq     = (const float*)d_in[3];
    const float* Wk     = (const float*)d_in[4];
    const float* bk     = (const float*)d_in[5];
    const float* Wv     = (const float*)d_in[6];
    const float* bv     = (const float*)d_in[7];
    const float* Wo     = (const float*)d_in[8];
    const float* bo     = (const float*)d_in[9];
    const float* W1     = (const float*)d_in[10];
    const float* ln1_s  = (const float*)d_in[11];
    const float* ln1_b  = (const float*)d_in[12];
    const float* W2     = (const float*)d_in[13];
    const float* b2     = (const float*)d_in[14];
    const float* ln2_s  = (const float*)d_in[15];
    const float* ln2_b  = (const float*)d_in[16];
    const float* Worb_r = (const float*)d_in[17];
    const float* Worb_i = (const float*)d_in[18];

    cudaFuncSetAttribute(pair_kernel, cudaFuncAttributeMaxDynamicSharedMemorySize, SMEM_BYTES);

    init_kernel<<<1, 1>>>();
    pair_kernel<<<NBLOCKS, 256, SMEM_BYTES>>>(electrons, W_in, Wq, bq, Wk, bk, Wv, bv,
                                              Wo, bo, W1, ln1_s, ln1_b, W2, b2,
                                              ln2_s, ln2_b, Worb_r, Worb_i);
    cusp_bos_kernel<<<NE, NE>>>(electrons);
    lu_kernel<<<1, 1024>>>();
    finalize_kernel<<<1, 1>>>((float*)d_out);
}

// round 2
// speedup vs baseline: 1.0102x; 1.0102x over previous
#include <cuda_runtime.h>
#include <math.h>

#define NE  256
#define DD  256
#define NH  4
#define DHD 64
#define NL  2
#define P_TOTAL (NE*(NE-1)/2)        /* 32640 */
#define PPB 8
#define NBLOCKS (P_TOTAL/PPB)        /* 4080 */
#define SMEM_BYTES (4*PPB*2*256*4)   /* 65536: h,q,k,v */

// ---------------- scratch (device globals; no allocations) ----------------
__device__ float2 g_A[NE*NE];
__device__ double g_acc[2];          // bosonic log sum (re, im)
__device__ double g_lu_logabs, g_lu_arg;
__device__ int    g_lu_par;

__device__ __forceinline__ float f4c(const float4& v, int u) {
    return u==0 ? v.x : (u==1 ? v.y : (u==2 ? v.z : v.w));
}

// out[p][s][tid] accumulator: acc[p][s] = sum_e in[p][s][e] * W[e*256+tid]
__device__ __forceinline__ void gemm256(const float* __restrict__ W,
                                        const float* in, float acc[PPB][2], int tid)
{
    #pragma unroll
    for (int p = 0; p < PPB; p++) { acc[p][0] = 0.f; acc[p][1] = 0.f; }
    for (int e = 0; e < 256; e += 4) {
        float4 hv[PPB][2];
        #pragma unroll
        for (int p = 0; p < PPB; p++) {
            hv[p][0] = *(const float4*)(in + (p*2+0)*256 + e);
            hv[p][1] = *(const float4*)(in + (p*2+1)*256 + e);
        }
        #pragma unroll
        for (int u = 0; u < 4; u++) {
            float w = __ldg(W + (e+u)*256 + tid);
            #pragma unroll
            for (int p = 0; p < PPB; p++) {
                acc[p][0] = fmaf(f4c(hv[p][0], u), w, acc[p][0]);
                acc[p][1] = fmaf(f4c(hv[p][1], u), w, acc[p][1]);
            }
        }
    }
}

__device__ __forceinline__ void layernorm(float* shh,
                                          const float* __restrict__ sc,
                                          const float* __restrict__ bi,
                                          float red[PPB][2][2][8], int tid)
{
    int lane = tid & 31, wrp = tid >> 5;
    float x[PPB][2];
    #pragma unroll
    for (int p = 0; p < PPB; p++) {
        #pragma unroll
        for (int s = 0; s < 2; s++) {
            float v = shh[(p*2+s)*256 + tid];
            x[p][s] = v;
            float s1 = v, s2 = v*v;
            #pragma unroll
            for (int off = 16; off; off >>= 1) {
                s1 += __shfl_xor_sync(0xffffffffu, s1, off);
                s2 += __shfl_xor_sync(0xffffffffu, s2, off);
            }
            if (lane == 0) { red[p][s][0][wrp] = s1; red[p][s][1][wrp] = s2; }
        }
    }
    __syncthreads();
    float scv = __ldg(sc + tid), biv = __ldg(bi + tid);
    #pragma unroll
    for (int p = 0; p < PPB; p++) {
        #pragma unroll
        for (int s = 0; s < 2; s++) {
            float s1 = 0.f, s2 = 0.f;
            #pragma unroll
            for (int w = 0; w < 8; w++) { s1 += red[p][s][0][w]; s2 += red[p][s][1][w]; }
            float m   = s1 * (1.f/256.f);
            float var = s2 * (1.f/256.f) - m*m;
            shh[(p*2+s)*256 + tid] = (x[p][s] - m) * rsqrtf(var + 1e-5f) * scv + biv;
        }
    }
    __syncthreads();
}

// ---------------- pair transformer + orbitals -> antisymmetric A ----------
__global__ void __launch_bounds__(256, 2) pair_kernel(
    const float* __restrict__ electrons,
    const float* __restrict__ W_in,
    const float* __restrict__ Wq, const float* __restrict__ bq,
    const float* __restrict__ Wk, const float* __restrict__ bk,
    const float* __restrict__ Wv, const float* __restrict__ bv,
    const float* __restrict__ Wo, const float* __restrict__ bo,
    const float* __restrict__ W1, const float* __restrict__ ln1_s, const float* __restrict__ ln1_b,
    const float* __restrict__ W2, const float* __restrict__ b2,
    const float* __restrict__ ln2_s, const float* __restrict__ ln2_b,
    const float* __restrict__ Worb_r, const float* __restrict__ Worb_i)
{
    extern __shared__ float smem[];
    float* shh = smem;
    float* shq = shh + PPB*2*256;
    float* shk = shq + PPB*2*256;
    float* shv = shk + PPB*2*256;

    __shared__ float s_attn[PPB][NH][2][2];
    __shared__ float s_feat[PPB][2][3];
    __shared__ float s_tp[PPB][2][2];
    __shared__ int   s_ij[PPB][2];
    __shared__ float s_red[PPB][2][2][8];
    __shared__ float s_orb[PPB][8];

    int tid = threadIdx.x;

    if (tid < PPB) {
        long long p = (long long)blockIdx.x * PPB + tid;
        double pd = (double)p;
        int i = (int)floor((2.0*NE - 1.0 - sqrt((2.0*NE-1.0)*(2.0*NE-1.0) - 8.0*pd)) * 0.5);
        if (i < 0) i = 0;
        if (i > NE-2) i = NE-2;
        while (i > 0 && (long long)i*(2*NE-1-i)/2 > p) i--;
        while ((long long)(i+1)*(2*NE-1-(i+1))/2 <= p) i++;
        long long base = (long long)i*(2*NE-1-i)/2;
        int j = (int)(p - base) + i + 1;
        s_ij[tid][0] = i; s_ij[tid][1] = j;
    }
    __syncthreads();
    if (tid < PPB*2) {
        int p = tid >> 1, s = tid & 1;
        int e = s_ij[p][s];
        float th = electrons[2*e], ph = electrons[2*e+1];
        s_tp[p][s][0] = th; s_tp[p][s][1] = ph;
        float st, ct, sp, cp;
        sincosf(th, &st, &ct);
        sincosf(ph, &sp, &cp);
        s_feat[p][s][0] = ct;
        s_feat[p][s][1] = st*cp;
        s_feat[p][s][2] = st*sp;
    }
    __syncthreads();

    // h = feat @ W_in
    {
        float w0 = __ldg(W_in + tid), w1 = __ldg(W_in + 256 + tid), w2 = __ldg(W_in + 512 + tid);
        #pragma unroll
        for (int p = 0; p < PPB; p++)
            #pragma unroll
            for (int s = 0; s < 2; s++)
                shh[(p*2+s)*256 + tid] = s_feat[p][s][0]*w0 + s_feat[p][s][1]*w1 + s_feat[p][s][2]*w2;
    }
    __syncthreads();

    float acc[PPB][2];
    for (int l = 0; l < NL; l++) {
        const float* Wq_l = Wq + l*65536;  const float* bq_l = bq + l*256;
        const float* Wk_l = Wk + l*65536;  const float* bk_l = bk + l*256;
        const float* Wv_l = Wv + l*65536;  const float* bv_l = bv + l*256;
        const float* Wo_l = Wo + l*65536;  const float* bo_l = bo + l*256;
        const float* W1_l = W1 + l*65536;
        const float* W2_l = W2 + l*65536;  const float* b2_l = b2 + l*256;

        gemm256(Wq_l, shh, acc, tid);
        { float b = __ldg(bq_l + tid);
          #pragma unroll
          for (int p = 0; p < PPB; p++) { shq[(p*2+0)*256+tid] = acc[p][0]+b; shq[(p*2+1)*256+tid] = acc[p][1]+b; } }
        gemm256(Wk_l, shh, acc, tid);
        { float b = __ldg(bk_l + tid);
          #pragma unroll
          for (int p = 0; p < PPB; p++) { shk[(p*2+0)*256+tid] = acc[p][0]+b; shk[(p*2+1)*256+tid] = acc[p][1]+b; } }
        gemm256(Wv_l, shh, acc, tid);
        { float b = __ldg(bv_l + tid);
          #pragma unroll
          for (int p = 0; p < PPB; p++) { shv[(p*2+0)*256+tid] = acc[p][0]+b; shv[(p*2+1)*256+tid] = acc[p][1]+b; } }
        __syncthreads();

        // attention (seq len 2, 4 heads)
        if (tid < PPB*8) {
            int p = tid >> 3, r = tid & 7, hh = r >> 1, s = r & 1;
            const float* qv = shq + (p*2+s)*256 + hh*DHD;
            const float* k0 = shk + (p*2+0)*256 + hh*DHD;
            const float* k1 = shk + (p*2+1)*256 + hh*DHD;
            float l0 = 0.f, l1 = 0.f;
            #pragma unroll 8
            for (int d = 0; d < DHD; d++) { float q = qv[d]; l0 = fmaf(q, k0[d], l0); l1 = fmaf(q, k1[d], l1); }
            l0 *= 0.125f; l1 *= 0.125f;
            float mx = fmaxf(l0, l1);
            float e0 = expf(l0 - mx), e1 = expf(l1 - mx);
            float inv = 1.f / (e0 + e1);
            s_attn[p][hh][s][0] = e0 * inv;
            s_attn[p][hh][s][1] = e1 * inv;
        }
        __syncthreads();

        // o = attn @ v  (overwrite shq)
        {
            int hh = tid >> 6;
            #pragma unroll
            for (int p = 0; p < PPB; p++) {
                float v0 = shv[(p*2+0)*256+tid], v1 = shv[(p*2+1)*256+tid];
                shq[(p*2+0)*256+tid] = s_attn[p][hh][0][0]*v0 + s_attn[p][hh][0][1]*v1;
                shq[(p*2+1)*256+tid] = s_attn[p][hh][1][0]*v0 + s_attn[p][hh][1][1]*v1;
            }
        }
        __syncthreads();

        // mha = o @ Wo + bo -> shk
        gemm256(Wo_l, shq, acc, tid);
        { float b = __ldg(bo_l + tid);
          #pragma unroll
          for (int p = 0; p < PPB; p++) { shk[(p*2+0)*256+tid] = acc[p][0]+b; shk[(p*2+1)*256+tid] = acc[p][1]+b; } }
        __syncthreads();

        // h += mha @ W1
        gemm256(W1_l, shk, acc, tid);
        #pragma unroll
        for (int p = 0; p < PPB; p++) { shh[(p*2+0)*256+tid] += acc[p][0]; shh[(p*2+1)*256+tid] += acc[p][1]; }
        __syncthreads();
        layernorm(shh, ln1_s + l*256, ln1_b + l*256, s_red, tid);

        // h += tanh(h @ W2 + b2)
        gemm256(W2_l, shh, acc, tid);
        __syncthreads();
        { float b = __ldg(b2_l + tid);
          #pragma unroll
          for (int p = 0; p < PPB; p++) {
              shh[(p*2+0)*256+tid] += tanhf(acc[p][0] + b);
              shh[(p*2+1)*256+tid] += tanhf(acc[p][1] + b);
          } }
        __syncthreads();
        layernorm(shh, ln2_s + l*256, ln2_b + l*256, s_red, tid);
    }

    // orbital projections: 8 warps = (ri, s, c) combos
    {
        int wrp = tid >> 5, lane = tid & 31;
        const float* Ws = (wrp >= 4) ? Worb_i : Worb_r;
        int s = (wrp >> 1) & 1, c = wrp & 1;
        for (int p = 0; p < PPB; p++) {
            float sum = 0.f;
            for (int d = lane; d < 256; d += 32)
                sum = fmaf(shh[(p*2+s)*256 + d], __ldg(Ws + d*2 + c), sum);
            #pragma unroll
            for (int off = 16; off; off >>= 1) sum += __shfl_xor_sync(0xffffffffu, sum, off);
            if (lane == 0) s_orb[p][wrp] = sum;
        }
    }
    __syncthreads();

    if (tid < PPB) {
        int p = tid;
        float th0 = s_tp[p][0][0], ph0 = s_tp[p][0][1];
        float th1 = s_tp[p][1][0], ph1 = s_tp[p][1][1];
        float c0, s0, c1, s1;
        sincosf(0.5f*th0, &s0, &c0);
        sincosf(0.5f*th1, &s1, &c1);
        float hd = 0.5f*(ph0 - ph1);
        float chd, shd; sincosf(hd, &shd, &chd);
        float re = (c0*s1 - c1*s0) * chd;
        float im = (c0*s1 + c1*s0) * shd;
        float chord2 = re*re + im*im;
        float trunc = 1.f - expf(-100.f * chord2);
        float t2 = trunc * trunc;
        float a_r = s_orb[p][0], b_r = s_orb[p][1], c_r = s_orb[p][2], d_r = s_orb[p][3];
        float a_i = s_orb[p][4], b_i = s_orb[p][5], c_i = s_orb[p][6], d_i = s_orb[p][7];
        // det of [[o00,o01],[o10,o11]], o_sc = (real idx s*2+c, imag idx 4+s*2+c)
        float det_r = (a_r*d_r - a_i*d_i) - (b_r*c_r - b_i*c_i);
        float det_i = (a_r*d_i + a_i*d_r) - (b_r*c_i + b_i*c_r);
        det_r *= t2; det_i *= t2;
        int i = s_ij[p][0], j = s_ij[p][1];
        g_A[i*NE + j] = make_float2(det_r, det_i);
        g_A[j*NE + i] = make_float2(-det_r, -det_i);
    }
}

// ---------------- cusp matrix + bosonic log sum ---------------------------
__global__ void cusp_bos_kernel(const float* __restrict__ electrons)
{
    int i = blockIdx.x, j = threadIdx.x;
    __shared__ double s_red[2][8];
    float thi = electrons[2*i], phi_ = electrons[2*i+1];
    float thj = electrons[2*j], phj  = electrons[2*j+1];
    float ci, si, cj, sj;
    sincosf(0.5f*thi, &si, &ci);
    sincosf(0.5f*thj, &sj, &cj);
    float hd = 0.5f*(phi_ - phj);
    float chd, shd; sincosf(hd, &shd, &chd);
    float er = (ci*sj - si*cj) * chd;
    float ei = (ci*sj + si*cj) * shd;

    float eye = (i == j) ? 1.f : 0.f;
    float cr = er + eye, cim = ei;
    float rc2 = cr*cr + cim*cim;
    float g = expf(-100.f * rc2);
    float2 a = (i == j) ? make_float2(0.f, 0.f) : g_A[i*NE + j];
    a.x += cr * g;
    a.y += cim * g;
    g_A[i*NE + j] = a;

    double lr = 0.0, li = 0.0;
    if (i != j) {
        float rho2 = er*er + ei*ei;
        lr = 0.5 * log((double)(0.01f + rho2));   // log|masked|
        li = (double)atan2f(ei, er);              // arg(masked) = arg(elem)
    }
    int lane = j & 31, wrp = j >> 5;
    #pragma unroll
    for (int off = 16; off; off >>= 1) {
        lr += __shfl_xor_sync(0xffffffffu, lr, off);
        li += __shfl_xor_sync(0xffffffffu, li, off);
    }
    if (lane == 0) { s_red[0][wrp] = lr; s_red[1][wrp] = li; }
    __syncthreads();
    if (j == 0) {
        double a0 = 0.0, a1 = 0.0;
        #pragma unroll
        for (int w = 0; w < 8; w++) { a0 += s_red[0][w]; a1 += s_red[1][w]; }
        atomicAdd(&g_acc[0], a0);
        atomicAdd(&g_acc[1], a1);
    }
}

// ---------------- complex LU with partial pivoting (slogdet) --------------
__device__ __forceinline__ float2 cmul(float2 a, float2 b) {
    return make_float2(a.x*b.x - a.y*b.y, a.x*b.y + a.y*b.x);
}

__global__ void __launch_bounds__(1024) lu_kernel()
{
    __shared__ float2 s_prow[256];
    __shared__ float2 s_l[256];
    __shared__ float  s_mx[8];
    __shared__ int    s_mi[8];
    __shared__ float2 s_inv;
    __shared__ int    s_piv;
    int tid = threadIdx.x;
    double logabs = 0.0, argsum = 0.0;
    int par = 0;

    for (int k = 0; k < 256; k++) {
        if (tid < 256) {
            float v = -1.f; int idx = tid;
            if (tid >= k) { float2 a = g_A[tid*256 + k]; v = fabsf(a.x) + fabsf(a.y); }
            #pragma unroll
            for (int off = 16; off; off >>= 1) {
                float ov = __shfl_xor_sync(0xffffffffu, v, off);
                int   oi = __shfl_xor_sync(0xffffffffu, idx, off);
                if (ov > v) { v = ov; idx = oi; }
            }
            if ((tid & 31) == 0) { s_mx[tid>>5] = v; s_mi[tid>>5] = idx; }
        }
        __syncthreads();
        if (tid == 0) {
            float bv = -1.f; int bi = k;
            #pragma unroll
            for (int w = 0; w < 8; w++) if (s_mx[w] > bv) { bv = s_mx[w]; bi = s_mi[w]; }
            s_piv = bi;
        }
        __syncthreads();
        int pv = s_piv;
        if (pv != k && tid < 256) {
            float2 t = g_A[k*256 + tid];
            g_A[k*256 + tid] = g_A[pv*256 + tid];
            g_A[pv*256 + tid] = t;
        }
        __syncthreads();
        if (tid == 0) {
            if (pv != k) par ^= 1;
            float2 u = g_A[k*256 + k];
            double n2 = (double)u.x*u.x + (double)u.y*u.y;
            logabs += 0.5 * log(n2);
            argsum += atan2((double)u.y, (double)u.x);
            float d = u.x*u.x + u.y*u.y;
            s_inv = make_float2(u.x/d, -u.y/d);
        }
        __syncthreads();
        if (tid < 256) {
            s_prow[tid] = g_A[k*256 + tid];
            if (tid > k) {
                float2 l = cmul(g_A[tid*256 + k], s_inv);
                s_l[tid] = l;
                g_A[tid*256 + k] = l;
            }
        }
        __syncthreads();
        {
            int c = tid & 255, r0 = tid >> 8;
            if (c > k) {
                float2 pr = s_prow[c];
                #pragma unroll 4
                for (int i = k + 1 + r0; i < 256; i += 4) {
                    float2 l = s_l[i];
                    float2 a = g_A[i*256 + c];
                    a.x -= l.x*pr.x - l.y*pr.y;
                    a.y -= l.x*pr.y + l.y*pr.x;
                    g_A[i*256 + c] = a;
                }
            }
        }
        __syncthreads();
    }
    if (tid == 0) { g_lu_logabs = logabs; g_lu_arg = argsum; g_lu_par = par; }
}

// ---------------- init + finalize -----------------------------------------
__global__ void init_kernel() { g_acc[0] = 0.0; g_acc[1] = 0.0; }

__global__ void finalize_kernel(float* out)
{
    const double PI = 3.14159265358979323846;
    double logabs = g_lu_logabs;
    double arg = g_lu_arg + (g_lu_par ? PI : 0.0);
    double w = fmod(arg, 2.0*PI);
    if (w >  PI) w -= 2.0*PI;
    if (w <= -PI) w += 2.0*PI;
    out[0] = (float)(0.5*logabs + g_acc[0]);
    out[1] = (float)(0.5*w      + g_acc[1]);
}

// ---------------- launch ---------------------------------------------------
extern "C" void kernel_launch(void* const* d_in, const int* in_sizes, int n_in,
                              void* d_out, int out_size)
{
    const float* electrons = (const float*)d_in[0];
    const float* W_in   = (const float*)d_in[1];
    const float* Wq     = (const float*)d_in[2];
    const float* bq     = (const float*)d_in[3];
    const float* Wk     = (const float*)d_in[4];
    const float* bk     = (const float*)d_in[5];
    const float* Wv     = (const float*)d_in[6];
    const float* bv     = (const float*)d_in[7];
    const float* Wo     = (const float*)d_in[8];
    const float* bo     = (const float*)d_in[9];
    const float* W1     = (const float*)d_in[10];
    const float* ln1_s  = (const float*)d_in[11];
    const float* ln1_b  = (const float*)d_in[12];
    const float* W2     = (const float*)d_in[13];
    const float* b2     = (const float*)d_in[14];
    const float* ln2_s  = (const float*)d_in[15];
    const float* ln2_b  = (const float*)d_in[16];
    const float* Worb_r = (const float*)d_in[17];
    const float* Worb_i = (const float*)d_in[18];

    cudaFuncSetAttribute(pair_kernel, cudaFuncAttributeMaxDynamicSharedMemorySize, SMEM_BYTES);

    init_kernel<<<1, 1>>>();
    pair_kernel<<<NBLOCKS, 256, SMEM_BYTES>>>(electrons, W_in, Wq, bq, Wk, bk, Wv, bv,
                                              Wo, bo, W1, ln1_s, ln1_b, W2, b2,
                                              ln2_s, ln2_b, Worb_r, Worb_i);
    cusp_bos_kernel<<<NE, NE>>>(electrons);
    lu_kernel<<<1, 1024>>>();
    finalize_kernel<<<1, 1>>>((float*)d_out);
}